// round 14
// baseline (speedup 1.0000x reference)
#include <cuda_runtime.h>
#include <cstdint>

// TextEmbedding: gather [B,S,W,D] from table, per-token LayerNorm, sum over W.
// B=32, S=128, W=32, D=256  -> out [B*S, D] f32.
//
// R14: at the measured LTS ceiling (~9.4 TB/s; 138.7 MB irreducible traffic
// -> ~14.8 us floor). This variant halves hot-loop MIO/FP work (8 reduction
// chains per position instead of 16) to chase DVFS/energy margin:
// chunk = 4 words (8 cp16/group), STAGES=2 ping-pong, distance 1, WPB=4,
// R6's proven 4-word fold reduction fed from smem.

#define DIM 256
#define WORDS 32
#define EPS 1e-12f
#define STAGES 2
#define NCHUNK 8            // 4 words per chunk
#define WPB 4               // warps per block

typedef unsigned long long u64;

__device__ __forceinline__ u64 pack2(float lo, float hi) {
    u64 r; asm("mov.b64 %0, {%1, %2};" : "=l"(r) : "f"(lo), "f"(hi)); return r;
}
__device__ __forceinline__ void unpack2(u64 v, float& lo, float& hi) {
    asm("mov.b64 {%0, %1}, %2;" : "=f"(lo), "=f"(hi) : "l"(v));
}
__device__ __forceinline__ u64 add2(u64 a, u64 b) {
    u64 d; asm("add.rn.f32x2 %0, %1, %2;" : "=l"(d) : "l"(a), "l"(b)); return d;
}
__device__ __forceinline__ u64 mul2(u64 a, u64 b) {
    u64 d; asm("mul.rn.f32x2 %0, %1, %2;" : "=l"(d) : "l"(a), "l"(b)); return d;
}
__device__ __forceinline__ u64 fma2(u64 a, u64 b, u64 c) {
    u64 d; asm("fma.rn.f32x2 %0, %1, %2, %3;" : "=l"(d) : "l"(a), "l"(b), "l"(c)); return d;
}

__device__ __forceinline__ void cp16(uint32_t dst_smem, const void* src) {
    asm volatile("cp.async.cg.shared.global [%0], [%1], 16;"
                 :: "r"(dst_smem), "l"(src));
}
__device__ __forceinline__ void cp_commit() {
    asm volatile("cp.async.commit_group;");
}
template <int N> __device__ __forceinline__ void cp_wait() {
    asm volatile("cp.async.wait_group %0;" :: "n"(N));
}

__global__ __launch_bounds__(32 * WPB)
void emb_ln_sum_kernel(const int* __restrict__ ids,
                       const float* __restrict__ table,
                       const float* __restrict__ gamma,
                       const float* __restrict__ beta,
                       float* __restrict__ out) {
    // [warp][stage][slot][lane] : slot k = {w0.lo, w0.hi, w1.lo, w1.hi,
    //                                       w2.lo, w2.hi, w3.lo, w3.hi}
    __shared__ float4 buf[WPB][STAGES][8][32];

    const int tid  = threadIdx.x;
    const int warp = tid >> 5;
    const int lane = tid & 31;
    const int pos  = blockIdx.x * WPB + warp;   // 0..4095

    // Lane L holds id of word L (one coalesced LDG.32 per warp).
    const int id_lane = __ldg(ids + pos * WORDS + lane);

    const uint32_t sbase =
        (uint32_t)__cvta_generic_to_shared(&buf[warp][0][0][lane]);
    const uint32_t stage_stride = 8 * 32 * sizeof(float4);  // 4096 B
    const uint32_t slot_stride  = 32 * sizeof(float4);      // 512 B

    // Producer: chunk c (words 4c..4c+3); each cp16 is 512B contiguous
    // across the warp (lane address = row + 4*lane floats).
    auto issue = [&](int c) {
        const uint32_t s = sbase + (uint32_t)(c & 1) * stage_stride;
        #pragma unroll
        for (int j = 0; j < 4; j++) {
            const int id = __shfl_sync(0xffffffffu, id_lane, 4 * c + j);
            const float* row = table + (size_t)id * DIM + 4 * lane;
            cp16(s + (2 * j)     * slot_stride, row);
            cp16(s + (2 * j + 1) * slot_stride, row + 128);
        }
        cp_commit();
    };

    u64 acc[4];
    const u64 z = pack2(0.0f, 0.0f);
    acc[0] = z; acc[1] = z; acc[2] = z; acc[3] = z;
    float mtot = 0.0f;

    issue(0);

    #pragma unroll
    for (int c = 0; c < NCHUNK; c++) {
        if (c + 1 < NCHUNK) { issue(c + 1); cp_wait<1>(); }
        else                cp_wait<0>();

        // Lane reads back its own dims (conflict-free LDS.128).
        const float4* sp = &buf[warp][c & 1][0][lane];
        float4 R[8];
        #pragma unroll
        for (int k = 0; k < 8; k++) R[k] = sp[32 * k];

        // Per-lane partials: v = {s0,q0, s1,q1, s2,q2, s3,q3}
        float v[8];
        #pragma unroll
        for (int wi = 0; wi < 4; wi++) {
            const float4 ra = R[2 * wi], rb = R[2 * wi + 1];
            const u64 a01 = pack2(ra.x, ra.y), a23 = pack2(ra.z, ra.w);
            const u64 b01 = pack2(rb.x, rb.y), b23 = pack2(rb.z, rb.w);
            const u64 s2 = add2(add2(a01, a23), add2(b01, b23));
            const u64 q2 = fma2(a01, a01, fma2(a23, a23, fma2(b01, b01, mul2(b23, b23))));
            float sl, sh, ql, qh;
            unpack2(s2, sl, sh); unpack2(q2, ql, qh);
            v[2 * wi] = sl + sh; v[2 * wi + 1] = ql + qh;
        }

        // Fold reduction: 8 values -> 1 per lane across lane bits 16, 8, 4.
        const bool hi16 = (lane & 16) != 0;
        float w4[4];
        #pragma unroll
        for (int j = 0; j < 4; j++) {
            float send = hi16 ? v[j] : v[j + 4];
            float keep = hi16 ? v[j + 4] : v[j];
            w4[j] = keep + __shfl_xor_sync(0xffffffffu, send, 16);
        }
        const bool hi8 = (lane & 8) != 0;
        float w2[2];
        #pragma unroll
        for (int j = 0; j < 2; j++) {
            float send = hi8 ? w4[j] : w4[j + 2];
            float keep = hi8 ? w4[j + 2] : w4[j];
            w2[j] = keep + __shfl_xor_sync(0xffffffffu, send, 8);
        }
        const bool hi4 = (lane & 4) != 0;
        float y;
        {
            float send = hi4 ? w2[0] : w2[1];
            float keep = hi4 ? w2[1] : w2[0];
            y = keep + __shfl_xor_sync(0xffffffffu, send, 4);
        }
        y += __shfl_xor_sync(0xffffffffu, y, 2);
        y += __shfl_xor_sync(0xffffffffu, y, 1);
        // Lane holds: word W = 2*b16 + b8; b4=0 -> s_W, b4=1 -> q_W.

        const float p  = __shfl_xor_sync(0xffffffffu, y, 4);
        const float s_ = hi4 ? p : y;
        const float q_ = hi4 ? y : p;
        const float mu  = s_ * (1.0f / 256.0f);
        const float var = q_ * (1.0f / 256.0f) - mu * mu;
        const float r_  = rsqrtf(var + EPS);
        const float msh = -mu * r_;

        // Chunk's total shift over its 4 words.
        float mc = msh + __shfl_xor_sync(0xffffffffu, msh, 8);
        mc += __shfl_xor_sync(0xffffffffu, mc, 16);
        mtot += mc;

        // Broadcast rstd for words 0..3 (source lanes 0, 8, 16, 24); packed acc.
        #pragma unroll
        for (int wi = 0; wi < 4; wi++) {
            const float rw = __shfl_sync(0xffffffffu, r_, wi * 8);
            const u64 rr = pack2(rw, rw);
            acc[0] = fma2(pack2(R[2 * wi].x,     R[2 * wi].y),     rr, acc[0]);
            acc[1] = fma2(pack2(R[2 * wi].z,     R[2 * wi].w),     rr, acc[1]);
            acc[2] = fma2(pack2(R[2 * wi + 1].x, R[2 * wi + 1].y), rr, acc[2]);
            acc[3] = fma2(pack2(R[2 * wi + 1].z, R[2 * wi + 1].w), rr, acc[3]);
        }
    }

    // out = (acc + mtot) * gamma + 32 * beta, per lane dims.
    float a0, a1, a2, a3, a4, a5, a6, a7;
    unpack2(acc[0], a0, a1); unpack2(acc[1], a2, a3);
    unpack2(acc[2], a4, a5); unpack2(acc[3], a6, a7);

    const float4 g0  = __ldg((const float4*)gamma + lane);
    const float4 g1  = __ldg((const float4*)gamma + 32 + lane);
    const float4 bt0 = __ldg((const float4*)beta + lane);
    const float4 bt1 = __ldg((const float4*)beta + 32 + lane);

    float4 o0, o1;
    o0.x = fmaf(a0 + mtot, g0.x, 32.0f * bt0.x);
    o0.y = fmaf(a1 + mtot, g0.y, 32.0f * bt0.y);
    o0.z = fmaf(a2 + mtot, g0.z, 32.0f * bt0.z);
    o0.w = fmaf(a3 + mtot, g0.w, 32.0f * bt0.w);
    o1.x = fmaf(a4 + mtot, g1.x, 32.0f * bt1.x);
    o1.y = fmaf(a5 + mtot, g1.y, 32.0f * bt1.y);
    o1.z = fmaf(a6 + mtot, g1.z, 32.0f * bt1.z);
    o1.w = fmaf(a7 + mtot, g1.w, 32.0f * bt1.w);

    float4* op = (float4*)(out + (size_t)pos * DIM);
    op[lane]      = o0;   // dims [4*lane, 4*lane+4)
    op[32 + lane] = o1;   // dims [128+4*lane, ...)
}

extern "C" void kernel_launch(void* const* d_in, const int* in_sizes, int n_in,
                              void* d_out, int out_size) {
    const int*   ids   = (const int*)d_in[0];     // [32,128,32] int32
    const float* table = (const float*)d_in[1];   // [32000,256] f32
    const float* gamma = (const float*)d_in[2];   // [256]
    const float* beta  = (const float*)d_in[3];   // [256]
    float* out = (float*)d_out;                   // [32,128,256] f32

    const int n_pos = in_sizes[0] / WORDS;        // 4096
    emb_ln_sum_kernel<<<n_pos / WPB, 32 * WPB>>>(ids, table, gamma, beta, out);
}

// round 15
// speedup vs baseline: 1.1555x; 1.1555x over previous
#include <cuda_runtime.h>
#include <cstdint>

// TextEmbedding: gather [B,S,W,D] from table, per-token LayerNorm, sum over W.
// B=32, S=128, W=32, D=256  -> out [B*S, D] f32.
//
// FINAL (champion, 14.85us): warp-per-position; contiguous cp.async.cg
// producer (each LDGSTS = 512B contiguous across the warp), 3-stage smem
// ring at prefetch distance 2 (2 words/chunk), fold warp reduction, packed
// f32x2 accumulate, gamma/beta factored out of the word loop. regs=56.
//
// This sits at the measured chip-level LTS ceiling: 138.7 MB irreducible L2
// traffic / 14.85us = 9.34 TB/s ~= 6300 B/cyc (path-independent cap; TMA
// would hit the same wall). Three independent architectures converge here.

#define DIM 256
#define WORDS 32
#define EPS 1e-12f
#define STAGES 3
#define NCHUNK 16           // 2 words per chunk
#define WPB 4               // warps per block

typedef unsigned long long u64;

__device__ __forceinline__ u64 pack2(float lo, float hi) {
    u64 r; asm("mov.b64 %0, {%1, %2};" : "=l"(r) : "f"(lo), "f"(hi)); return r;
}
__device__ __forceinline__ void unpack2(u64 v, float& lo, float& hi) {
    asm("mov.b64 {%0, %1}, %2;" : "=f"(lo), "=f"(hi) : "l"(v));
}
__device__ __forceinline__ u64 add2(u64 a, u64 b) {
    u64 d; asm("add.rn.f32x2 %0, %1, %2;" : "=l"(d) : "l"(a), "l"(b)); return d;
}
__device__ __forceinline__ u64 mul2(u64 a, u64 b) {
    u64 d; asm("mul.rn.f32x2 %0, %1, %2;" : "=l"(d) : "l"(a), "l"(b)); return d;
}
__device__ __forceinline__ u64 fma2(u64 a, u64 b, u64 c) {
    u64 d; asm("fma.rn.f32x2 %0, %1, %2, %3;" : "=l"(d) : "l"(a), "l"(b), "l"(c)); return d;
}

__device__ __forceinline__ void cp16(uint32_t dst_smem, const void* src) {
    asm volatile("cp.async.cg.shared.global [%0], [%1], 16;"
                 :: "r"(dst_smem), "l"(src));
}
__device__ __forceinline__ void cp_commit() {
    asm volatile("cp.async.commit_group;");
}
template <int N> __device__ __forceinline__ void cp_wait() {
    asm volatile("cp.async.wait_group %0;" :: "n"(N));
}

__global__ __launch_bounds__(32 * WPB)
void emb_ln_sum_kernel(const int* __restrict__ ids,
                       const float* __restrict__ table,
                       const float* __restrict__ gamma,
                       const float* __restrict__ beta,
                       float* __restrict__ out) {
    // [warp][stage][slot][lane] : slot = {w0.lo, w0.hi, w1.lo, w1.hi}
    __shared__ float4 buf[WPB][STAGES][4][32];

    const int tid  = threadIdx.x;
    const int warp = tid >> 5;
    const int lane = tid & 31;
    const int pos  = blockIdx.x * WPB + warp;   // 0..4095

    // Lane L holds id of word L (one coalesced LDG.32 per warp).
    const int id_lane = __ldg(ids + pos * WORDS + lane);

    const uint32_t sbase =
        (uint32_t)__cvta_generic_to_shared(&buf[warp][0][0][lane]);
    const uint32_t stage_stride = 4 * 32 * sizeof(float4);  // 2048 B
    const uint32_t slot_stride  = 32 * sizeof(float4);      // 512 B

    // Producer: chunk c (words 2c, 2c+1); each cp16 is 512B contiguous
    // across the warp (lane address = row + 4*lane floats).
    auto issue = [&](int c) {
        const int id0 = __shfl_sync(0xffffffffu, id_lane, 2 * c);
        const int id1 = __shfl_sync(0xffffffffu, id_lane, 2 * c + 1);
        const float* r0 = table + (size_t)id0 * DIM + 4 * lane;
        const float* r1 = table + (size_t)id1 * DIM + 4 * lane;
        const uint32_t s = sbase + (uint32_t)(c % STAGES) * stage_stride;
        cp16(s,                   r0);
        cp16(s + slot_stride,     r0 + 128);
        cp16(s + 2 * slot_stride, r1);
        cp16(s + 3 * slot_stride, r1 + 128);
        cp_commit();
    };

    u64 acc[4];
    const u64 z = pack2(0.0f, 0.0f);
    acc[0] = z; acc[1] = z; acc[2] = z; acc[3] = z;
    float mtot = 0.0f;

    issue(0);
    issue(1);

    #pragma unroll
    for (int c = 0; c < NCHUNK; c++) {
        if (c + 2 < NCHUNK) issue(c + 2);

        // Wait until chunk c's group has landed.
        if (c + 2 < NCHUNK)      cp_wait<2>();
        else if (c + 1 < NCHUNK) cp_wait<1>();
        else                     cp_wait<0>();

        // Read this lane's own bytes back from smem (conflict-free LDS.128).
        const float4* sp = &buf[warp][c % STAGES][0][lane];
        const float4 R0 = sp[0];
        const float4 R1 = sp[32];
        const float4 R2 = sp[64];
        const float4 R3 = sp[96];

        // Per-lane partials: v = {s0, q0, s1, q1}
        float v[4];
        {
            const u64 a01 = pack2(R0.x, R0.y), a23 = pack2(R0.z, R0.w);
            const u64 b01 = pack2(R1.x, R1.y), b23 = pack2(R1.z, R1.w);
            const u64 s2 = add2(add2(a01, a23), add2(b01, b23));
            const u64 q2 = fma2(a01, a01, fma2(a23, a23, fma2(b01, b01, mul2(b23, b23))));
            float sl, sh, ql, qh;
            unpack2(s2, sl, sh); unpack2(q2, ql, qh);
            v[0] = sl + sh; v[1] = ql + qh;
        }
        {
            const u64 a01 = pack2(R2.x, R2.y), a23 = pack2(R2.z, R2.w);
            const u64 b01 = pack2(R3.x, R3.y), b23 = pack2(R3.z, R3.w);
            const u64 s2 = add2(add2(a01, a23), add2(b01, b23));
            const u64 q2 = fma2(a01, a01, fma2(a23, a23, fma2(b01, b01, mul2(b23, b23))));
            float sl, sh, ql, qh;
            unpack2(s2, sl, sh); unpack2(q2, ql, qh);
            v[2] = sl + sh; v[3] = ql + qh;
        }

        // Fold: bit16 selects word, bit8 selects s/q; butterfly 4,2,1.
        const bool hi16 = (lane & 16) != 0;
        float w2[2];
        #pragma unroll
        for (int j = 0; j < 2; j++) {
            float send = hi16 ? v[j] : v[j + 2];
            float keep = hi16 ? v[j + 2] : v[j];
            w2[j] = keep + __shfl_xor_sync(0xffffffffu, send, 16);
        }
        const bool hi8 = (lane & 8) != 0;
        float y;
        {
            float send = hi8 ? w2[0] : w2[1];
            float keep = hi8 ? w2[1] : w2[0];
            y = keep + __shfl_xor_sync(0xffffffffu, send, 8);
        }
        y += __shfl_xor_sync(0xffffffffu, y, 4);
        y += __shfl_xor_sync(0xffffffffu, y, 2);
        y += __shfl_xor_sync(0xffffffffu, y, 1);
        // Lane holds: word W = b16; b8 = 0 -> s_W, b8 = 1 -> q_W.

        const float p  = __shfl_xor_sync(0xffffffffu, y, 8);
        const float s_ = hi8 ? p : y;
        const float q_ = hi8 ? y : p;
        const float mu  = s_ * (1.0f / 256.0f);
        const float var = q_ * (1.0f / 256.0f) - mu * mu;
        const float r_  = rsqrtf(var + EPS);
        const float msh = -mu * r_;

        mtot += msh + __shfl_xor_sync(0xffffffffu, msh, 16);

        const float r0 = __shfl_sync(0xffffffffu, r_, 0);
        const float r1 = __shfl_sync(0xffffffffu, r_, 16);
        const u64 rr0 = pack2(r0, r0);
        const u64 rr1 = pack2(r1, r1);
        acc[0] = fma2(pack2(R0.x, R0.y), rr0, acc[0]);
        acc[1] = fma2(pack2(R0.z, R0.w), rr0, acc[1]);
        acc[2] = fma2(pack2(R1.x, R1.y), rr0, acc[2]);
        acc[3] = fma2(pack2(R1.z, R1.w), rr0, acc[3]);
        acc[0] = fma2(pack2(R2.x, R2.y), rr1, acc[0]);
        acc[1] = fma2(pack2(R2.z, R2.w), rr1, acc[1]);
        acc[2] = fma2(pack2(R3.x, R3.y), rr1, acc[2]);
        acc[3] = fma2(pack2(R3.z, R3.w), rr1, acc[3]);
    }

    // out = (acc + mtot) * gamma + 32 * beta, per lane dims.
    float a0, a1, a2, a3, a4, a5, a6, a7;
    unpack2(acc[0], a0, a1); unpack2(acc[1], a2, a3);
    unpack2(acc[2], a4, a5); unpack2(acc[3], a6, a7);

    const float4 g0  = __ldg((const float4*)gamma + lane);
    const float4 g1  = __ldg((const float4*)gamma + 32 + lane);
    const float4 bt0 = __ldg((const float4*)beta + lane);
    const float4 bt1 = __ldg((const float4*)beta + 32 + lane);

    float4 o0, o1;
    o0.x = fmaf(a0 + mtot, g0.x, 32.0f * bt0.x);
    o0.y = fmaf(a1 + mtot, g0.y, 32.0f * bt0.y);
    o0.z = fmaf(a2 + mtot, g0.z, 32.0f * bt0.z);
    o0.w = fmaf(a3 + mtot, g0.w, 32.0f * bt0.w);
    o1.x = fmaf(a4 + mtot, g1.x, 32.0f * bt1.x);
    o1.y = fmaf(a5 + mtot, g1.y, 32.0f * bt1.y);
    o1.z = fmaf(a6 + mtot, g1.z, 32.0f * bt1.z);
    o1.w = fmaf(a7 + mtot, g1.w, 32.0f * bt1.w);

    float4* op = (float4*)(out + (size_t)pos * DIM);
    op[lane]      = o0;   // dims [4*lane, 4*lane+4)
    op[32 + lane] = o1;   // dims [128+4*lane, ...)
}

extern "C" void kernel_launch(void* const* d_in, const int* in_sizes, int n_in,
                              void* d_out, int out_size) {
    const int*   ids   = (const int*)d_in[0];     // [32,128,32] int32
    const float* table = (const float*)d_in[1];   // [32000,256] f32
    const float* gamma = (const float*)d_in[2];   // [256]
    const float* beta  = (const float*)d_in[3];   // [256]
    float* out = (float*)d_out;                   // [32,128,256] f32

    const int n_pos = in_sizes[0] / WORDS;        // 4096
    emb_ln_sum_kernel<<<n_pos / WPB, 32 * WPB>>>(ids, table, gamma, beta, out);
}